// round 13
// baseline (speedup 1.0000x reference)
#include <cuda_runtime.h>
#include <math.h>

#define HH 1024
#define LL 128
#define VOCAB 50257
#define LTHR 640
#define LWARPS 20
#define KROWS 18   // 148*20*18 = 53280 >= VOCAB

// ---------------- device scratch (no allocations allowed) ----------------
__device__ float g_scores[LL];
__device__ float g_attn[HH];
__device__ float g_gru_in[HH];
__device__ float g_gh[3 * HH];
__device__ float g_gi[3 * HH];
__device__ float g_bmax[256], g_bsum[256];
__device__ unsigned g_sdone[256];
__device__ unsigned g_flags[256];
__device__ unsigned g_flags2[256];

__device__ __forceinline__ float warp_sum(float v) {
#pragma unroll
    for (int o = 16; o > 0; o >>= 1) v += __shfl_down_sync(0xffffffffu, v, o);
    return v;
}

// symmetric store/poll barrier: every block's warp 0 sweeps all flags
__device__ __forceinline__ void grid_bar_sym(int nb, int bid, int t, int lane,
                                             int wid, unsigned gen) {
    __syncthreads();
    if (t == 0) {
        __threadfence();
        ((volatile unsigned*)g_flags)[bid] = gen;
    }
    if (wid == 0) {
        bool ok;
        do {
            ok = true;
            for (int i = lane; i < nb; i += 32)
                if (((volatile unsigned*)g_flags)[i] < gen) ok = false;
            ok = __all_sync(0xffffffffu, ok);
        } while (!ok);
        __threadfence();
    }
    __syncthreads();
}

__device__ __forceinline__ void lse_combine(float& M, float& S, float m2, float s2) {
    if (m2 == -INFINITY) return;
    if (m2 > M) { S = S * expf(M - m2) + s2; M = m2; }
    else        { S += s2 * expf(m2 - M); }
}

__device__ __forceinline__ float dot_buf8(const float* __restrict__ row,
                                          const float* __restrict__ vec, int lane) {
    const float4* r4 = (const float4*)row;
    const float4* v4 = (const float4*)vec;
    float4 w[8];
#pragma unroll
    for (int i = 0; i < 8; i++) w[i] = r4[lane + 32 * i];
    float acc = 0.f;
#pragma unroll
    for (int i = 0; i < 8; i++) {
        const float4 v = v4[lane + 32 * i];
        acc += w[i].x*v.x + w[i].y*v.y + w[i].z*v.z + w[i].w*v.w;
    }
    return warp_sum(acc);
}

__device__ __forceinline__ float dot_buf16(const float* __restrict__ row,
                                           const float* __restrict__ vec, int lane) {
    const float4* r4 = (const float4*)row;
    const float4* v4 = (const float4*)vec;
    float4 w[8];
    float acc = 0.f;
#pragma unroll
    for (int i = 0; i < 8; i++) w[i] = r4[lane + 32 * i];
#pragma unroll
    for (int i = 0; i < 8; i++) {
        const float4 v = v4[lane + 32 * i];
        acc += w[i].x*v.x + w[i].y*v.y + w[i].z*v.z + w[i].w*v.w;
    }
#pragma unroll
    for (int i = 0; i < 8; i++) w[i] = r4[lane + 32 * (i + 8)];
#pragma unroll
    for (int i = 0; i < 8; i++) {
        const float4 v = v4[lane + 32 * (i + 8)];
        acc += w[i].x*v.x + w[i].y*v.y + w[i].z*v.z + w[i].w*v.w;
    }
    return warp_sum(acc);
}

// ================= K1: chain P0..P3 (persistent 148 x 1024) ===============
__global__ void __launch_bounds__(1024, 1)
k_chain(const int* __restrict__ ids,
        const float* __restrict__ hidden,
        const float* __restrict__ enc,
        const float* __restrict__ emb,
        const float* __restrict__ attn_W,
        const float* __restrict__ attn_b,
        const float* __restrict__ comb_W,
        const float* __restrict__ comb_b,
        const float* __restrict__ W_ih,
        const float* __restrict__ W_hh,
        const float* __restrict__ b_ih,
        const float* __restrict__ b_hh,
        float* __restrict__ out) {
    const int nb = gridDim.x;
    const int t = threadIdx.x, wid = t >> 5, lane = t & 31, bid = blockIdx.x;
    const int task = wid * nb + bid;

    __shared__ float s_vec[2 * HH];
    __shared__ float s_red[1024];
    __shared__ float s_w[LL];
    __shared__ float s_m[2];
    __shared__ float s_bm[32], s_bs[32];

    const size_t qb = (size_t)ids[0] * HH;
    if (t < 256)      ((float4*)s_vec)[t] = ((const float4*)(emb + qb))[t];
    else if (t < 512) ((float4*)s_vec)[t] = ((const float4*)hidden)[t - 256];
    __syncthreads();

    // P0: gh rows (3072 tasks) + attn scores (128)
    if (task < 3 * HH) {
        const float a = dot_buf8(W_hh + (size_t)task * HH, s_vec + HH, lane);
        if (lane == 0) g_gh[task] = a + b_hh[task];
    } else if (task < 3 * HH + LL) {
        const int l = task - 3 * HH;
        const float a = dot_buf16(attn_W + (size_t)l * 2 * HH, s_vec, lane);
        if (lane == 0) g_scores[l] = a + attn_b[l];
    }
    grid_bar_sym(nb, bid, t, lane, wid, 1u);

    // P1: softmax + attn_applied (blocks 0..7)
    if (bid < 8) {
        float sc = (t < LL) ? g_scores[t] : -INFINITY;
        if (t < LL) {
            float v = sc;
#pragma unroll
            for (int o = 16; o > 0; o >>= 1) v = fmaxf(v, __shfl_down_sync(0xffffffffu, v, o));
            if (lane == 0) s_bm[wid] = v;
        }
        __syncthreads();
        if (t == 0) s_m[0] = fmaxf(fmaxf(s_bm[0], s_bm[1]), fmaxf(s_bm[2], s_bm[3]));
        __syncthreads();
        float e = 0.f;
        if (t < LL) {
            e = expf(sc - s_m[0]);
            float v = warp_sum(e);
            if (lane == 0) s_bs[wid] = v;
        }
        __syncthreads();
        if (t == 0) s_m[1] = 1.f / (s_bs[0] + s_bs[1] + s_bs[2] + s_bs[3]);
        __syncthreads();
        if (t < LL) {
            s_w[t] = e * s_m[1];
            if (bid == 0) out[VOCAB + HH + t] = s_w[t];
        }
        __syncthreads();
        const int col = t & 127, lg = t >> 7;
        const int colg = bid * 128 + col;
        float acc = 0.f;
#pragma unroll
        for (int k = 0; k < 16; k++) {
            const int l = lg * 16 + k;
            acc += s_w[l] * enc[(size_t)l * HH + colg];
        }
        s_red[t] = acc;
        __syncthreads();
        if (t < 128) {
            float a = 0.f;
#pragma unroll
            for (int k = 0; k < 8; k++) a += s_red[t + 128 * k];
            g_attn[colg] = a;
        }
    }
    grid_bar_sym(nb, bid, t, lane, wid, 2u);

    // P2: gru_in = relu([q; attn] @ comb_W.T + b)
    if (t < 256) ((float4*)s_vec)[256 + t] = ((const float4*)g_attn)[t];
    __syncthreads();
    if (task < HH) {
        const float a = dot_buf16(comb_W + (size_t)task * 2 * HH, s_vec, lane);
        if (lane == 0) g_gru_in[task] = fmaxf(a + comb_b[task], 0.f);
    }
    grid_bar_sym(nb, bid, t, lane, wid, 3u);

    // P3: gi rows (3072 tasks) — consumed by k_logits after kernel boundary
    if (t < 256) ((float4*)s_vec)[t] = ((const float4*)g_gru_in)[t];
    __syncthreads();
    if (task < 3 * HH) {
        const float a = dot_buf8(W_ih + (size_t)task * HH, s_vec, lane);
        if (lane == 0) g_gi[task] = a;
    }

    // epilogue: block 0 alone waits for all, then resets flags
    __syncthreads();
    if (t == 0) {
        __threadfence();
        ((volatile unsigned*)g_flags)[bid] = 4u;
    }
    if (bid == 0 && wid == 0) {
        bool ok;
        do {
            ok = true;
            for (int i = lane; i < nb; i += 32)
                if (((volatile unsigned*)g_flags)[i] < 4u) ok = false;
            ok = __all_sync(0xffffffffu, ok);
        } while (!ok);
        for (int i = lane; i < nb; i += 32) ((volatile unsigned*)g_flags)[i] = 0u;
    }
}

// ================= K2: GRU gates + logits (persistent 148 x 640) ==========
__global__ void __launch_bounds__(LTHR, 1)
k_logits(const float* __restrict__ hidden,
         const float* __restrict__ b_ih,
         const float* __restrict__ b_hh,
         const float* __restrict__ out_W,
         const float* __restrict__ out_b,
         float* __restrict__ out) {
    const int nb = gridDim.x;
    const int t = threadIdx.x, wid = t >> 5, lane = t & 31, bid = blockIdx.x;
    const int wg = bid * LWARPS + wid;
    const int base = wg * KROWS;

    __shared__ float s_h[HH];
    __shared__ float s_bm[LWARPS], s_bs[LWARPS];
    __shared__ float s_lse;

    // ---- redundant per-block GRU gate math -> s_h = h_new ----
    for (int j = t; j < HH; j += LTHR) {
        const float ir  = g_gi[j]          + b_ih[j];
        const float iz  = g_gi[j + HH]     + b_ih[j + HH];
        const float inn = g_gi[j + 2 * HH] + b_ih[j + 2 * HH];
        const float r = 1.f / (1.f + expf(-(ir + g_gh[j])));
        const float z = 1.f / (1.f + expf(-(iz + g_gh[j + HH])));
        const float n = tanhf(inn + r * g_gh[j + 2 * HH]);
        const float hnew = (1.f - z) * n + z * hidden[j];
        s_h[j] = hnew;
        if (bid == 0) out[VOCAB + j] = hnew;
    }
    __syncthreads();
    const float4* v4 = (const float4*)s_h;

    // ---- main loop: A/B double-buffered, no reductions inside ----
    float acc[KROWS];
#pragma unroll
    for (int k = 0; k < KROWS; k++) acc[k] = 0.f;

    float4 A[8], B[8];
    {
        const int r0 = min(base, VOCAB - 1);
        const float4* r4 = (const float4*)(out_W + (size_t)r0 * HH);
#pragma unroll
        for (int i = 0; i < 8; i++) A[i] = __ldcs(r4 + lane + 32 * i);
    }
#pragma unroll
    for (int k = 0; k < KROWS; k += 2) {
        {
            const int r1 = min(base + k + 1, VOCAB - 1);
            const float4* r4 = (const float4*)(out_W + (size_t)r1 * HH);
#pragma unroll
            for (int i = 0; i < 8; i++) B[i] = __ldcs(r4 + lane + 32 * i);
        }
#pragma unroll
        for (int i = 0; i < 8; i++) {
            const float4 v = v4[lane + 32 * i];
            acc[k] += A[i].x*v.x + A[i].y*v.y + A[i].z*v.z + A[i].w*v.w;
        }
        if (k + 2 < KROWS) {
            const int r2 = min(base + k + 2, VOCAB - 1);
            const float4* r4 = (const float4*)(out_W + (size_t)r2 * HH);
#pragma unroll
            for (int i = 0; i < 8; i++) A[i] = __ldcs(r4 + lane + 32 * i);
        }
#pragma unroll
        for (int i = 0; i < 8; i++) {
            const float4 v = v4[lane + 32 * i];
            acc[k + 1] += B[i].x*v.x + B[i].y*v.y + B[i].z*v.z + B[i].w*v.w;
        }
    }

    // ---- deferred reductions ----
#pragma unroll
    for (int k = 0; k < KROWS; k++) acc[k] = warp_sum(acc[k]);

    // ---- stats ----
    float m = -INFINITY, s = 0.f;
    if (lane == 0) {
#pragma unroll
        for (int k = 0; k < KROWS; k++) {
            const int r = base + k;
            if (r < VOCAB) lse_combine(m, s, acc[k] + out_b[r], 1.f);
        }
        s_bm[wid] = m; s_bs[wid] = s;
    }
    __syncthreads();
    if (wid == 0) {
        float M = (lane < LWARPS) ? s_bm[lane] : -INFINITY;
        float S = (lane < LWARPS) ? s_bs[lane] : 0.f;
#pragma unroll
        for (int o = 16; o > 0; o >>= 1) {
            float m2 = __shfl_down_sync(0xffffffffu, M, o);
            float s2 = __shfl_down_sync(0xffffffffu, S, o);
            lse_combine(M, S, m2, s2);
        }
        if (lane == 0) {
            g_bmax[bid] = M; g_bsum[bid] = S;
            __threadfence();
            ((volatile unsigned*)g_sdone)[bid] = 1u;
        }
    }

    // ---- all resident blocks poll stats, compute LSE redundantly ----
    if (wid == 0) {
        bool ok;
        do {
            ok = true;
            for (int i = lane; i < nb; i += 32)
                if (((volatile unsigned*)g_sdone)[i] == 0u) ok = false;
            ok = __all_sync(0xffffffffu, ok);
        } while (!ok);
        __threadfence();
        float M = -INFINITY, S = 0.f;
        for (int i = lane; i < nb; i += 32)
            lse_combine(M, S, ((volatile float*)g_bmax)[i], ((volatile float*)g_bsum)[i]);
#pragma unroll
        for (int o = 16; o > 0; o >>= 1) {
            float m2 = __shfl_down_sync(0xffffffffu, M, o);
            float s2 = __shfl_down_sync(0xffffffffu, S, o);
            lse_combine(M, S, m2, s2);
        }
        if (lane == 0) s_lse = M + logf(S);
    }
    __syncthreads();

    // ---- write log_probs from registers ----
    {
        const float lse = s_lse;
        if (lane == 0) {
#pragma unroll
            for (int k = 0; k < KROWS; k++) {
                const int r = base + k;
                if (r < VOCAB) out[r] = acc[k] + out_b[r] - lse;
            }
        }
    }

    // ---- epilogue: reset sdone ----
    __syncthreads();
    if (t == 0) {
        __threadfence();
        ((volatile unsigned*)g_flags2)[bid] = 1u;
    }
    if (bid == 0 && wid == 0) {
        bool ok;
        do {
            ok = true;
            for (int i = lane; i < nb; i += 32)
                if (((volatile unsigned*)g_flags2)[i] == 0u) ok = false;
            ok = __all_sync(0xffffffffu, ok);
        } while (!ok);
        for (int i = lane; i < nb; i += 32) {
            ((volatile unsigned*)g_sdone)[i] = 0u;
            ((volatile unsigned*)g_flags2)[i] = 0u;
        }
    }
}

extern "C" void kernel_launch(void* const* d_in, const int* in_sizes, int n_in,
                              void* d_out, int out_size) {
    const int*   ids    = (const int*)  d_in[0];
    const float* hidden = (const float*)d_in[1];
    const float* enc    = (const float*)d_in[2];
    const float* emb    = (const float*)d_in[3];
    const float* attn_W = (const float*)d_in[4];
    const float* attn_b = (const float*)d_in[5];
    const float* comb_W = (const float*)d_in[6];
    const float* comb_b = (const float*)d_in[7];
    const float* W_ih   = (const float*)d_in[8];
    const float* W_hh   = (const float*)d_in[9];
    const float* b_ih   = (const float*)d_in[10];
    const float* b_hh   = (const float*)d_in[11];
    const float* out_W  = (const float*)d_in[12];
    const float* out_b  = (const float*)d_in[13];
    float* out = (float*)d_out;

    int dev = 0, nsm = 148;
    cudaGetDevice(&dev);
    cudaDeviceGetAttribute(&nsm, cudaDevAttrMultiProcessorCount, dev);

    k_chain<<<nsm, 1024>>>(ids, hidden, enc, emb, attn_W, attn_b,
                           comb_W, comb_b, W_ih, W_hh, b_ih, b_hh, out);
    k_logits<<<nsm, LTHR>>>(hidden, b_ih, b_hh, out_W, out_b, out);
}

// round 14
// speedup vs baseline: 1.0076x; 1.0076x over previous
#include <cuda_runtime.h>
#include <math.h>

#define HH 1024
#define LL 128
#define VOCAB 50257
#define LTHR 512
#define LWARPS 16
#define KROWS 22   // 148*16*22 = 52096 >= VOCAB

// ---------------- device scratch (no allocations allowed) ----------------
__device__ float g_scores[LL];
__device__ float g_attn[HH];
__device__ float g_gru_in[HH];
__device__ float g_gh[3 * HH];
__device__ float g_gi[3 * HH];
__device__ float g_bmax[256], g_bsum[256];
__device__ unsigned g_sdone[256];
__device__ unsigned g_flags[256];
__device__ unsigned g_flags2[256];

__device__ __forceinline__ float warp_sum(float v) {
#pragma unroll
    for (int o = 16; o > 0; o >>= 1) v += __shfl_down_sync(0xffffffffu, v, o);
    return v;
}

// symmetric store/poll barrier: every block's warp 0 sweeps all flags
__device__ __forceinline__ void grid_bar_sym(int nb, int bid, int t, int lane,
                                             int wid, unsigned gen) {
    __syncthreads();
    if (t == 0) {
        __threadfence();
        ((volatile unsigned*)g_flags)[bid] = gen;
    }
    if (wid == 0) {
        bool ok;
        do {
            ok = true;
            for (int i = lane; i < nb; i += 32)
                if (((volatile unsigned*)g_flags)[i] < gen) ok = false;
            ok = __all_sync(0xffffffffu, ok);
        } while (!ok);
        __threadfence();
    }
    __syncthreads();
}

__device__ __forceinline__ void lse_combine(float& M, float& S, float m2, float s2) {
    if (m2 == -INFINITY) return;
    if (m2 > M) { S = S * expf(M - m2) + s2; M = m2; }
    else        { S += s2 * expf(m2 - M); }
}

__device__ __forceinline__ float dot_buf8(const float* __restrict__ row,
                                          const float* __restrict__ vec, int lane) {
    const float4* r4 = (const float4*)row;
    const float4* v4 = (const float4*)vec;
    float4 w[8];
#pragma unroll
    for (int i = 0; i < 8; i++) w[i] = r4[lane + 32 * i];
    float acc = 0.f;
#pragma unroll
    for (int i = 0; i < 8; i++) {
        const float4 v = v4[lane + 32 * i];
        acc += w[i].x*v.x + w[i].y*v.y + w[i].z*v.z + w[i].w*v.w;
    }
    return warp_sum(acc);
}

__device__ __forceinline__ float dot_buf16(const float* __restrict__ row,
                                           const float* __restrict__ vec, int lane) {
    const float4* r4 = (const float4*)row;
    const float4* v4 = (const float4*)vec;
    float4 w[8];
    float acc = 0.f;
#pragma unroll
    for (int i = 0; i < 8; i++) w[i] = r4[lane + 32 * i];
#pragma unroll
    for (int i = 0; i < 8; i++) {
        const float4 v = v4[lane + 32 * i];
        acc += w[i].x*v.x + w[i].y*v.y + w[i].z*v.z + w[i].w*v.w;
    }
#pragma unroll
    for (int i = 0; i < 8; i++) w[i] = r4[lane + 32 * (i + 8)];
#pragma unroll
    for (int i = 0; i < 8; i++) {
        const float4 v = v4[lane + 32 * (i + 8)];
        acc += w[i].x*v.x + w[i].y*v.y + w[i].z*v.z + w[i].w*v.w;
    }
    return warp_sum(acc);
}

// ================= K1: chain P0..P3 (persistent 148 x 1024) ===============
__global__ void __launch_bounds__(1024, 1)
k_chain(const int* __restrict__ ids,
        const float* __restrict__ hidden,
        const float* __restrict__ enc,
        const float* __restrict__ emb,
        const float* __restrict__ attn_W,
        const float* __restrict__ attn_b,
        const float* __restrict__ comb_W,
        const float* __restrict__ comb_b,
        const float* __restrict__ W_ih,
        const float* __restrict__ W_hh,
        const float* __restrict__ b_ih,
        const float* __restrict__ b_hh,
        float* __restrict__ out) {
    const int nb = gridDim.x;
    const int t = threadIdx.x, wid = t >> 5, lane = t & 31, bid = blockIdx.x;
    const int task = wid * nb + bid;

    __shared__ float s_vec[2 * HH];
    __shared__ float s_red[1024];
    __shared__ float s_w[LL];
    __shared__ float s_m[2];
    __shared__ float s_bm[32], s_bs[32];

    const size_t qb = (size_t)ids[0] * HH;
    if (t < 256)      ((float4*)s_vec)[t] = ((const float4*)(emb + qb))[t];
    else if (t < 512) ((float4*)s_vec)[t] = ((const float4*)hidden)[t - 256];
    __syncthreads();

    // P0: gh rows (3072 tasks) + attn scores (128)
    if (task < 3 * HH) {
        const float a = dot_buf8(W_hh + (size_t)task * HH, s_vec + HH, lane);
        if (lane == 0) g_gh[task] = a + b_hh[task];
    } else if (task < 3 * HH + LL) {
        const int l = task - 3 * HH;
        const float a = dot_buf16(attn_W + (size_t)l * 2 * HH, s_vec, lane);
        if (lane == 0) g_scores[l] = a + attn_b[l];
    }
    grid_bar_sym(nb, bid, t, lane, wid, 1u);

    // P1: softmax + attn_applied (blocks 0..7)
    if (bid < 8) {
        float sc = (t < LL) ? g_scores[t] : -INFINITY;
        if (t < LL) {
            float v = sc;
#pragma unroll
            for (int o = 16; o > 0; o >>= 1) v = fmaxf(v, __shfl_down_sync(0xffffffffu, v, o));
            if (lane == 0) s_bm[wid] = v;
        }
        __syncthreads();
        if (t == 0) s_m[0] = fmaxf(fmaxf(s_bm[0], s_bm[1]), fmaxf(s_bm[2], s_bm[3]));
        __syncthreads();
        float e = 0.f;
        if (t < LL) {
            e = expf(sc - s_m[0]);
            float v = warp_sum(e);
            if (lane == 0) s_bs[wid] = v;
        }
        __syncthreads();
        if (t == 0) s_m[1] = 1.f / (s_bs[0] + s_bs[1] + s_bs[2] + s_bs[3]);
        __syncthreads();
        if (t < LL) {
            s_w[t] = e * s_m[1];
            if (bid == 0) out[VOCAB + HH + t] = s_w[t];
        }
        __syncthreads();
        const int col = t & 127, lg = t >> 7;
        const int colg = bid * 128 + col;
        float acc = 0.f;
#pragma unroll
        for (int k = 0; k < 16; k++) {
            const int l = lg * 16 + k;
            acc += s_w[l] * enc[(size_t)l * HH + colg];
        }
        s_red[t] = acc;
        __syncthreads();
        if (t < 128) {
            float a = 0.f;
#pragma unroll
            for (int k = 0; k < 8; k++) a += s_red[t + 128 * k];
            g_attn[colg] = a;
        }
    }
    grid_bar_sym(nb, bid, t, lane, wid, 2u);

    // P2: gru_in = relu([q; attn] @ comb_W.T + b)
    if (t < 256) ((float4*)s_vec)[256 + t] = ((const float4*)g_attn)[t];
    __syncthreads();
    if (task < HH) {
        const float a = dot_buf16(comb_W + (size_t)task * 2 * HH, s_vec, lane);
        if (lane == 0) g_gru_in[task] = fmaxf(a + comb_b[task], 0.f);
    }
    grid_bar_sym(nb, bid, t, lane, wid, 3u);

    // P3: gi rows (3072 tasks) — consumed by k_logits after kernel boundary
    if (t < 256) ((float4*)s_vec)[t] = ((const float4*)g_gru_in)[t];
    __syncthreads();
    if (task < 3 * HH) {
        const float a = dot_buf8(W_ih + (size_t)task * HH, s_vec, lane);
        if (lane == 0) g_gi[task] = a;
    }

    // epilogue: block 0 alone waits for all, then resets flags
    __syncthreads();
    if (t == 0) {
        __threadfence();
        ((volatile unsigned*)g_flags)[bid] = 4u;
    }
    if (bid == 0 && wid == 0) {
        bool ok;
        do {
            ok = true;
            for (int i = lane; i < nb; i += 32)
                if (((volatile unsigned*)g_flags)[i] < 4u) ok = false;
            ok = __all_sync(0xffffffffu, ok);
        } while (!ok);
        for (int i = lane; i < nb; i += 32) ((volatile unsigned*)g_flags)[i] = 0u;
    }
}

// ================= K2: GRU gates + logits (persistent 148 x 512) ==========
__global__ void __launch_bounds__(LTHR, 1)
k_logits(const float* __restrict__ hidden,
         const float* __restrict__ b_ih,
         const float* __restrict__ b_hh,
         const float* __restrict__ out_W,
         const float* __restrict__ out_b,
         float* __restrict__ out) {
    const int nb = gridDim.x;
    const int t = threadIdx.x, wid = t >> 5, lane = t & 31, bid = blockIdx.x;
    const int wg = bid * LWARPS + wid;
    const int base = wg * KROWS;

    __shared__ float s_h[HH];
    __shared__ float s_bm[LWARPS], s_bs[LWARPS];
    __shared__ float s_lse;

    // ---- issue first two row loads BEFORE gate math (independent of h_new) -
    float4 A[8], B[8];
    {
        const int r0 = min(base, VOCAB - 1);
        const float4* r4 = (const float4*)(out_W + (size_t)r0 * HH);
#pragma unroll
        for (int i = 0; i < 8; i++) A[i] = __ldcs(r4 + lane + 32 * i);
    }
    {
        const int r1 = min(base + 1, VOCAB - 1);
        const float4* r4 = (const float4*)(out_W + (size_t)r1 * HH);
#pragma unroll
        for (int i = 0; i < 8; i++) B[i] = __ldcs(r4 + lane + 32 * i);
    }

    // ---- redundant per-block GRU gate math -> s_h = h_new (hidden by loads)-
    for (int j = t; j < HH; j += LTHR) {
        const float ir  = g_gi[j]          + b_ih[j];
        const float iz  = g_gi[j + HH]     + b_ih[j + HH];
        const float inn = g_gi[j + 2 * HH] + b_ih[j + 2 * HH];
        const float r = 1.f / (1.f + expf(-(ir + g_gh[j])));
        const float z = 1.f / (1.f + expf(-(iz + g_gh[j + HH])));
        const float n = tanhf(inn + r * g_gh[j + 2 * HH]);
        const float hnew = (1.f - z) * n + z * hidden[j];
        s_h[j] = hnew;
        if (bid == 0) out[VOCAB + j] = hnew;
    }
    __syncthreads();
    const float4* v4 = (const float4*)s_h;

    // ---- main loop: A/B double-buffered, no reductions inside ----
    float acc[KROWS];
#pragma unroll
    for (int k = 0; k < KROWS; k++) acc[k] = 0.f;

#pragma unroll
    for (int k = 0; k < KROWS; k += 2) {
        // FMA row k from A, then refill A with row k+2
#pragma unroll
        for (int i = 0; i < 8; i++) {
            const float4 v = v4[lane + 32 * i];
            acc[k] += A[i].x*v.x + A[i].y*v.y + A[i].z*v.z + A[i].w*v.w;
        }
        if (k + 2 < KROWS) {
            const int r2 = min(base + k + 2, VOCAB - 1);
            const float4* r4 = (const float4*)(out_W + (size_t)r2 * HH);
#pragma unroll
            for (int i = 0; i < 8; i++) A[i] = __ldcs(r4 + lane + 32 * i);
        }
        // FMA row k+1 from B, then refill B with row k+3
#pragma unroll
        for (int i = 0; i < 8; i++) {
            const float4 v = v4[lane + 32 * i];
            acc[k + 1] += B[i].x*v.x + B[i].y*v.y + B[i].z*v.z + B[i].w*v.w;
        }
        if (k + 3 < KROWS) {
            const int r3 = min(base + k + 3, VOCAB - 1);
            const float4* r4 = (const float4*)(out_W + (size_t)r3 * HH);
#pragma unroll
            for (int i = 0; i < 8; i++) B[i] = __ldcs(r4 + lane + 32 * i);
        }
    }

    // ---- deferred reductions ----
#pragma unroll
    for (int k = 0; k < KROWS; k++) acc[k] = warp_sum(acc[k]);

    // ---- stats ----
    float m = -INFINITY, s = 0.f;
    if (lane == 0) {
#pragma unroll
        for (int k = 0; k < KROWS; k++) {
            const int r = base + k;
            if (r < VOCAB) lse_combine(m, s, acc[k] + out_b[r], 1.f);
        }
        s_bm[wid] = m; s_bs[wid] = s;
    }
    __syncthreads();
    if (wid == 0) {
        float M = (lane < LWARPS) ? s_bm[lane] : -INFINITY;
        float S = (lane < LWARPS) ? s_bs[lane] : 0.f;
#pragma unroll
        for (int o = 16; o > 0; o >>= 1) {
            float m2 = __shfl_down_sync(0xffffffffu, M, o);
            float s2 = __shfl_down_sync(0xffffffffu, S, o);
            lse_combine(M, S, m2, s2);
        }
        if (lane == 0) {
            g_bmax[bid] = M; g_bsum[bid] = S;
            __threadfence();
            ((volatile unsigned*)g_sdone)[bid] = 1u;
        }
    }

    // ---- all resident blocks poll stats, compute LSE redundantly ----
    if (wid == 0) {
        bool ok;
        do {
            ok = true;
            for (int i = lane; i < nb; i += 32)
                if (((volatile unsigned*)g_sdone)[i] == 0u) ok = false;
            ok = __all_sync(0xffffffffu, ok);
        } while (!ok);
        __threadfence();
        float M = -INFINITY, S = 0.f;
        for (int i = lane; i < nb; i += 32)
            lse_combine(M, S, ((volatile float*)g_bmax)[i], ((volatile float*)g_bsum)[i]);
#pragma unroll
        for (int o = 16; o > 0; o >>= 1) {
            float m2 = __shfl_down_sync(0xffffffffu, M, o);
            float s2 = __shfl_down_sync(0xffffffffu, S, o);
            lse_combine(M, S, m2, s2);
        }
        if (lane == 0) s_lse = M + logf(S);
    }
    __syncthreads();

    // ---- write log_probs from registers ----
    {
        const float lse = s_lse;
        if (lane == 0) {
#pragma unroll
            for (int k = 0; k < KROWS; k++) {
                const int r = base + k;
                if (r < VOCAB) out[r] = acc[k] + out_b[r] - lse;
            }
        }
    }

    // ---- epilogue: reset sdone ----
    __syncthreads();
    if (t == 0) {
        __threadfence();
        ((volatile unsigned*)g_flags2)[bid] = 1u;
    }
    if (bid == 0 && wid == 0) {
        bool ok;
        do {
            ok = true;
            for (int i = lane; i < nb; i += 32)
                if (((volatile unsigned*)g_flags2)[i] == 0u) ok = false;
            ok = __all_sync(0xffffffffu, ok);
        } while (!ok);
        for (int i = lane; i < nb; i += 32) {
            ((volatile unsigned*)g_sdone)[i] = 0u;
            ((volatile unsigned*)g_flags2)[i] = 0u;
        }
    }
}

extern "C" void kernel_launch(void* const* d_in, const int* in_sizes, int n_in,
                              void* d_out, int out_size) {
    const int*   ids    = (const int*)  d_in[0];
    const float* hidden = (const float*)d_in[1];
    const float* enc    = (const float*)d_in[2];
    const float* emb    = (const float*)d_in[3];
    const float* attn_W = (const float*)d_in[4];
    const float* attn_b = (const float*)d_in[5];
    const float* comb_W = (const float*)d_in[6];
    const float* comb_b = (const float*)d_in[7];
    const float* W_ih   = (const float*)d_in[8];
    const float* W_hh   = (const float*)d_in[9];
    const float* b_ih   = (const float*)d_in[10];
    const float* b_hh   = (const float*)d_in[11];
    const float* out_W  = (const float*)d_in[12];
    const float* out_b  = (const float*)d_in[13];
    float* out = (float*)d_out;

    int dev = 0, nsm = 148;
    cudaGetDevice(&dev);
    cudaDeviceGetAttribute(&nsm, cudaDevAttrMultiProcessorCount, dev);

    k_chain<<<nsm, 1024>>>(ids, hidden, enc, emb, attn_W, attn_b,
                           comb_W, comb_b, W_ih, W_hh, b_ih, b_hh, out);
    k_logits<<<nsm, LTHR>>>(hidden, b_ih, b_hh, out_W, out_b, out);
}